// round 4
// baseline (speedup 1.0000x reference)
#include <cuda_runtime.h>
#include <cstdint>

// Problem constants (fixed shapes from reference)
#define BB_   2
#define CC_   64
#define DD_   31
#define HW_   16384                 // H*W = 128*128
#define CS_   507904                // channel stride = D*H*W
#define TILE_P 128                  // positions per CTA tile
#define N_TILES (BB_ * DD_ * (HW_ / TILE_P))   // 7936
#define DTILES (DD_ * (HW_ / TILE_P))          // 3968
#define GRID_ 296                   // persistent: 2 CTAs/SM * 148 SMs

#define STRIDE_ 136                 // padded row stride (floats): banks (8t+g)%32 -> conflict-free
#define STAGE_FLOATS (16 * STRIDE_) // one 16-channel x 128-pos staged chunk (padded) = 2176
#define NSTAGE 3

// SMEM layout (float offsets):
#define SM_W1 0                     // 8192  (w1 tf32, A-frag swizzled)
#define SM_W2 8192                  // 4096  (w2 tf32, A-frag swizzled)
#define SM_B1 12288                 // 64
#define SM_B2 12352                 // 64
#define SM_H  12416                 // 64*136 = 8704
#define SM_ST (12416 + 8704)        // 21120 : 3 stages * 2176
#define SM_FLOATS (SM_ST + NSTAGE * STAGE_FLOATS)   // 27648 floats = 110592 B (2 CTAs: 216 KB)

#define CP_WAIT(n) asm volatile("cp.async.wait_group %0;" :: "n"(n) : "memory")

__device__ __forceinline__ uint32_t f2tf(float f) {
    uint32_t u;
    asm("cvt.rna.tf32.f32 %0, %1;" : "=r"(u) : "f"(f));
    return u;
}
__device__ __forceinline__ float tanha(float v) {
    float r;
    asm("tanh.approx.f32 %0, %1;" : "=f"(r) : "f"(v));
    return r;
}
__device__ __forceinline__ void mma8(float& d0, float& d1, float& d2, float& d3,
                                     uint32_t a0, uint32_t a1, uint32_t a2, uint32_t a3,
                                     uint32_t b0, uint32_t b1) {
    asm("mma.sync.aligned.m16n8k8.row.col.f32.tf32.tf32.f32 "
        "{%0,%1,%2,%3}, {%4,%5,%6,%7}, {%8,%9}, {%0,%1,%2,%3};"
        : "+f"(d0), "+f"(d1), "+f"(d2), "+f"(d3)
        : "r"(a0), "r"(a1), "r"(a2), "r"(a3), "r"(b0), "r"(b1));
}

// Issue the cp.async loads for global chunk ci (8 chunks per tile: x c0..3, y c0..3).
// Always commits a group (possibly empty) so wait_group accounting stays exact.
__device__ __forceinline__ void issue_chunk(const float* __restrict__ x,
                                            const float* __restrict__ y,
                                            float* sm, int bid, int nT, int ci, int tid)
{
    if (ci < nT * 8) {
        const int j = ci >> 3, c = ci & 7;
        const int tile = bid + j * GRID_;
        const int bb  = tile / DTILES;
        const int rem = tile - bb * DTILES;
        const int dd  = rem >> 7;
        const int hw0 = (rem & 127) << 7;
        const size_t slab = ((size_t)(bb * CC_) * DD_ + dd) * (size_t)HW_;
        const float* src = (c < 4) ? x : y;
        const int chOff = (c & 3) * 16;
        float* dstBase = sm + SM_ST + (ci % NSTAGE) * STAGE_FLOATS;
        #pragma unroll
        for (int r = 0; r < 4; r++) {
            const int idx = tid + r * 128;
            const int ch = idx >> 5;          // 0..15
            const int q  = idx & 31;          // 16B quad within 128-pos row
            const float* gp = src + slab + (size_t)(chOff + ch) * CS_ + hw0 + q * 4;
            uint32_t da = (uint32_t)__cvta_generic_to_shared(dstBase + ch * STRIDE_ + q * 4);
            asm volatile("cp.async.cg.shared.global [%0], [%1], 16;" :: "r"(da), "l"(gp));
        }
    }
    asm volatile("cp.async.commit_group;" ::: "memory");
}

extern "C" __global__ void __launch_bounds__(128, 2)
ssaf_kernel(const float* __restrict__ x, const float* __restrict__ y,
            const float* __restrict__ w1, const float* __restrict__ b1,
            const float* __restrict__ w2, const float* __restrict__ b2,
            float* __restrict__ out)
{
    extern __shared__ float sm[];
    float* w1s = sm + SM_W1;
    float* w2s = sm + SM_W2;
    float* b1s = sm + SM_B1;
    float* b2s = sm + SM_B2;
    float* Hs  = sm + SM_H;

    const int tid  = threadIdx.x;
    const int wid  = tid >> 5;
    const int lane = tid & 31;
    const int t    = lane & 3;   // k index within fragment
    const int g    = lane >> 2;  // row/col index within fragment
    const int bid  = blockIdx.x;
    const int nT   = (N_TILES - bid + GRID_ - 1) / GRID_;

    // Kick off the input pipeline before touching weights (overlaps weight LDG latency).
    issue_chunk(x, y, sm, bid, nT, 0, tid);
    issue_chunk(x, y, sm, bid, nT, 1, tid);

    // ---- Load + tf32-convert weights into smem, pre-swizzled in A-fragment order ----
    // dest index i = ((kk*4 + mm)*32 + lane)*4 + j  ->  one LDS.128 per (kk,mm) per lane
    // frag regs: j=0:(g,t) j=1:(g+8,t) j=2:(g,t+4) j=3:(g+8,t+4)
    for (int i = tid; i < 8192; i += 128) {
        int kk = i >> 9; int rem = i & 511;
        int mm = rem >> 7; int l = (rem >> 2) & 31; int jj = rem & 3;
        int gg = l >> 2, tt = l & 3;
        int m = mm * 16 + gg + (jj & 1) * 8;
        int k = kk * 8 + tt + (jj >> 1) * 4;
        w1s[i] = __uint_as_float(f2tf(w1[m * 128 + k]));
    }
    for (int i = tid; i < 4096; i += 128) {
        int kk = i >> 9; int rem = i & 511;
        int mm = rem >> 7; int l = (rem >> 2) & 31; int jj = rem & 3;
        int gg = l >> 2, tt = l & 3;
        int m = mm * 16 + gg + (jj & 1) * 8;
        int k = kk * 8 + tt + (jj >> 1) * 4;
        w2s[i] = __uint_as_float(f2tf(w2[m * 64 + k]));
    }
    if (tid < 64) { b1s[tid] = b1[tid]; b2s[tid] = b2[tid]; }
    __syncthreads();

    const int wcol = wid * 32;   // warp's position offset within tile

    for (int j = 0; j < nT; j++) {
        const int tile = bid + j * GRID_;
        const int bb  = tile / DTILES;
        const int rem = tile - bb * DTILES;
        const int dd  = rem >> 7;
        const int hw0 = (rem & 127) << 7;
        const size_t slabBase = ((size_t)(bb * CC_) * DD_ + dd) * (size_t)HW_;

        // ---------------- GEMM1: H = tanh(W1 * [x;y] + b1) ----------------
        float acc[4][4][4];
        #pragma unroll
        for (int mm = 0; mm < 4; mm++) {
            const float bv0 = b1s[mm * 16 + g];
            const float bv1 = b1s[mm * 16 + g + 8];
            #pragma unroll
            for (int nt = 0; nt < 4; nt++) {
                acc[mm][nt][0] = bv0; acc[mm][nt][1] = bv0;
                acc[mm][nt][2] = bv1; acc[mm][nt][3] = bv1;
            }
        }

        // chunk loop: chunk c covers k-tiles {2c, 2c+1} of the concat(x,y) k-dim
        for (int c = 0; c < 8; c++) {
            const int ci = j * 8 + c;
            CP_WAIT(1);
            __syncthreads();                         // stage (ci%3) fully staged, all warps done with ci-1
            issue_chunk(x, y, sm, bid, nT, ci + 2, tid);   // refill stage (ci+2)%3

            const float* st = sm + SM_ST + (ci % NSTAGE) * STAGE_FLOATS;
            const float* bp0 = st + t * STRIDE_ + wcol + g;
            #pragma unroll
            for (int kkL = 0; kkL < 2; kkL++) {
                const int kk = 2 * c + kkL;
                const float* bp = bp0 + kkL * 8 * STRIDE_;
                uint32_t bf0[4], bf1[4];
                #pragma unroll
                for (int nt = 0; nt < 4; nt++) {
                    bf0[nt] = f2tf(bp[nt * 8]);
                    bf1[nt] = f2tf(bp[4 * STRIDE_ + nt * 8]);
                }
                #pragma unroll
                for (int mm = 0; mm < 4; mm++) {
                    const uint4 a = *(const uint4*)(w1s + ((kk * 4 + mm) * 32 + lane) * 4);
                    #pragma unroll
                    for (int nt = 0; nt < 4; nt++)
                        mma8(acc[mm][nt][0], acc[mm][nt][1], acc[mm][nt][2], acc[mm][nt][3],
                             a.x, a.y, a.z, a.w, bf0[nt], bf1[nt]);
                }
            }
        }

        // tanh -> store H to smem as tf32 bits (per-warp private columns -> no CTA barrier)
        #pragma unroll
        for (int mm = 0; mm < 4; mm++) {
            const int r0 = mm * 16 + g;
            #pragma unroll
            for (int nt = 0; nt < 4; nt++) {
                const int col = wcol + nt * 8 + 2 * t;
                float2 h0, h1;
                h0.x = __uint_as_float(f2tf(tanha(acc[mm][nt][0])));
                h0.y = __uint_as_float(f2tf(tanha(acc[mm][nt][1])));
                h1.x = __uint_as_float(f2tf(tanha(acc[mm][nt][2])));
                h1.y = __uint_as_float(f2tf(tanha(acc[mm][nt][3])));
                *(float2*)(Hs + r0 * STRIDE_ + col)       = h0;
                *(float2*)(Hs + (r0 + 8) * STRIDE_ + col) = h1;
            }
        }
        __syncwarp();

        // ---------------- GEMM2: U = W2 * H + b2 ----------------
        float acc2[4][4][4];
        #pragma unroll
        for (int mm = 0; mm < 4; mm++) {
            const float bv0 = b2s[mm * 16 + g];
            const float bv1 = b2s[mm * 16 + g + 8];
            #pragma unroll
            for (int nt = 0; nt < 4; nt++) {
                acc2[mm][nt][0] = bv0; acc2[mm][nt][1] = bv0;
                acc2[mm][nt][2] = bv1; acc2[mm][nt][3] = bv1;
            }
        }
        #pragma unroll
        for (int kk = 0; kk < 8; kk++) {
            uint32_t bf0[4], bf1[4];
            #pragma unroll
            for (int nt = 0; nt < 4; nt++) {
                bf0[nt] = __float_as_uint(Hs[(kk * 8 + t) * STRIDE_ + wcol + nt * 8 + g]);
                bf1[nt] = __float_as_uint(Hs[(kk * 8 + t + 4) * STRIDE_ + wcol + nt * 8 + g]);
            }
            #pragma unroll
            for (int mm = 0; mm < 4; mm++) {
                const uint4 a = *(const uint4*)(w2s + ((kk * 4 + mm) * 32 + lane) * 4);
                #pragma unroll
                for (int nt = 0; nt < 4; nt++)
                    mma8(acc2[mm][nt][0], acc2[mm][nt][1], acc2[mm][nt][2], acc2[mm][nt][3],
                         a.x, a.y, a.z, a.w, bf0[nt], bf1[nt]);
            }
        }

        // ---------------- Epilogue: out = x + sigmoid(U) * (y - x) ----------------
        // sigmoid(u) = 0.5 + 0.5*tanh(0.5*u); x,y re-reads are L2 hits.
        #pragma unroll
        for (int mm = 0; mm < 4; mm++) {
            #pragma unroll
            for (int nt = 0; nt < 4; nt++) {
                const int pcol = hw0 + wcol + nt * 8 + 2 * t;
                #pragma unroll
                for (int half = 0; half < 2; half++) {
                    const int r = mm * 16 + g + half * 8;
                    const size_t idx = slabBase + (size_t)r * CS_ + pcol;
                    const float u0 = acc2[mm][nt][half * 2 + 0];
                    const float u1 = acc2[mm][nt][half * 2 + 1];
                    const float g0 = 0.5f + 0.5f * tanha(0.5f * u0);
                    const float g1 = 0.5f + 0.5f * tanha(0.5f * u1);
                    const float2 xv = *(const float2*)(x + idx);
                    const float2 yv = *(const float2*)(y + idx);
                    float2 ov;
                    ov.x = fmaf(g0, yv.x - xv.x, xv.x);
                    ov.y = fmaf(g1, yv.y - xv.y, xv.y);
                    *(float2*)(out + idx) = ov;
                }
            }
        }
        // No barrier needed here: Hs columns are warp-private; staging hazards are
        // handled by the per-chunk barrier at the top of the next tile's chunk loop.
    }
}

extern "C" void kernel_launch(void* const* d_in, const int* in_sizes, int n_in,
                              void* d_out, int out_size)
{
    const float* x  = (const float*)d_in[0];
    const float* y  = (const float*)d_in[1];
    const float* w1 = (const float*)d_in[2];
    const float* b1 = (const float*)d_in[3];
    const float* w2 = (const float*)d_in[4];
    const float* b2 = (const float*)d_in[5];
    float* out = (float*)d_out;

    const int smem_bytes = SM_FLOATS * (int)sizeof(float);   // 110592 B
    cudaFuncSetAttribute(ssaf_kernel, cudaFuncAttributeMaxDynamicSharedMemorySize, smem_bytes);
    ssaf_kernel<<<GRID_, 128, smem_bytes>>>(x, y, w1, b1, w2, b2, out);
}